// round 6
// baseline (speedup 1.0000x reference)
#include <cuda_runtime.h>
#include <cuda_bf16.h>
#include <cuda_fp16.h>
#include <cstdint>
#include <math.h>

#define NV   100000
#define ME   50000
#define NNZE 800000
#define HD   128
#define NCLS 40
#define DEPTH 4

typedef unsigned long long u64;

// -------- scratch (no allocations allowed; __device__ globals) --------
__device__ float g_Xi[NV * HD];                      // blended GEMM input (fp32)
__device__ __align__(16) __half2 g_hb [NV * 64];     // h  packed fp16x2
__device__ __align__(16) __half2 g_h0b[NV * 64];     // x0 packed fp16x2
__device__ __align__(16) __half2 g_Xeb[ME * 64];     // Xe packed fp16x2
// weights pre-split to bf16 hi/lo in MMA fragment layout. slot0=W0, 1..4=folded
__device__ __align__(16) __nv_bfloat16 g_Bhi[5 * HD * HD];
__device__ __align__(16) __nv_bfloat16 g_Blo[5 * HD * HD];
__device__ int g_cnt_e[ME], g_cnt_v[NV];
__device__ int g_off_e[ME + 1], g_off_v[NV + 1];
__device__ int g_cur_e[ME], g_cur_v[NV];
__device__ int g_adj_e[NNZE];   // vertex ids grouped by edge
__device__ int g_adj_v[NNZE];   // edge ids grouped by vertex

// -------- f32x2 helpers (used by gemm_out) -----------------------------
__device__ __forceinline__ void ffma2(u64& d, u64 a, u64 b, u64 c) {
    asm("fma.rn.f32x2 %0, %1, %2, %3;" : "=l"(d) : "l"(a), "l"(b), "l"(c));
}
__device__ __forceinline__ u64 bcast2(float a) {
    u64 r;
    asm("mov.b64 %0, {%1, %1};" : "=l"(r) : "f"(a));
    return r;
}
__device__ __forceinline__ float2 unpack2(u64 u) {
    float2 f;
    asm("mov.b64 {%0, %1}, %2;" : "=f"(f.x), "=f"(f.y) : "l"(u));
    return f;
}

// -------- fp16/bf16 helpers ---------------------------------------------
__device__ __forceinline__ void bsplit(float a, __nv_bfloat16& hi, __nv_bfloat16& lo) {
    hi = __float2bfloat16_rn(a);
    lo = __float2bfloat16_rn(a - __bfloat162float(hi));
}
__device__ __forceinline__ float4 h4f(uint2 u) {
    __half2 p0 = *(__half2*)&u.x;
    __half2 p1 = *(__half2*)&u.y;
    float2 f0 = __half22float2(p0);
    float2 f1 = __half22float2(p1);
    return make_float4(f0.x, f0.y, f1.x, f1.y);
}
__device__ __forceinline__ uint2 f4h(float4 v) {
    __half2 p0 = __floats2half2_rn(v.x, v.y);
    __half2 p1 = __floats2half2_rn(v.z, v.w);
    uint2 u;
    u.x = *(uint32_t*)&p0;
    u.y = *(uint32_t*)&p1;
    return u;
}

// mma.sync m16n8k16 bf16 -> f32 accum
__device__ __forceinline__ void mma16816(float* d, const uint4& a, const uint2& b) {
    asm volatile(
        "mma.sync.aligned.m16n8k16.row.col.f32.bf16.bf16.f32 "
        "{%0,%1,%2,%3}, {%4,%5,%6,%7}, {%8,%9}, {%0,%1,%2,%3};"
        : "+f"(d[0]), "+f"(d[1]), "+f"(d[2]), "+f"(d[3])
        : "r"(a.x), "r"(a.y), "r"(a.z), "r"(a.w), "r"(b.x), "r"(b.y));
}

// ---------------------------------------------------------------------
__global__ void k_zero_counts() {
    int i = blockIdx.x * blockDim.x + threadIdx.x;
    if (i < ME) g_cnt_e[i] = 0;
    if (i < NV) g_cnt_v[i] = 0;
}

// 4 entries per thread, front-loaded (MLP-4)
__global__ void k_count4(const int* __restrict__ vtx, const int* __restrict__ edg) {
    int i = (blockIdx.x * blockDim.x + threadIdx.x) * 4;
    if (i >= NNZE) return;
    int4 e4 = *(const int4*)&edg[i];
    int4 v4 = *(const int4*)&vtx[i];
    atomicAdd(&g_cnt_e[e4.x], 1);
    atomicAdd(&g_cnt_e[e4.y], 1);
    atomicAdd(&g_cnt_e[e4.z], 1);
    atomicAdd(&g_cnt_e[e4.w], 1);
    atomicAdd(&g_cnt_v[v4.x], 1);
    atomicAdd(&g_cnt_v[v4.y], 1);
    atomicAdd(&g_cnt_v[v4.z], 1);
    atomicAdd(&g_cnt_v[v4.w], 1);
}

__global__ void k_scan() {
    const int which = blockIdx.x;
    const int len = which ? NV : ME;
    const int* cnt = which ? g_cnt_v : g_cnt_e;
    int* off = which ? g_off_v : g_off_e;
    int* cur = which ? g_cur_v : g_cur_e;

    __shared__ int sm[1024];
    int t = threadIdx.x;
    int chunk = (len + 1023) >> 10;
    int lo = t * chunk;
    int hi = min(lo + chunk, len);

    int s = 0;
    for (int i = lo; i < hi; i++) s += cnt[i];
    sm[t] = s;
    __syncthreads();
    for (int o = 1; o < 1024; o <<= 1) {
        int add = (t >= o) ? sm[t - o] : 0;
        __syncthreads();
        sm[t] += add;
        __syncthreads();
    }
    int excl = sm[t] - s;
    int run = excl;
    for (int i = lo; i < hi; i++) {
        off[i] = run;
        cur[i] = run;
        run += cnt[i];
    }
    if (t == 1023) off[len] = run;
}

__global__ void k_fill4(const int* __restrict__ vtx, const int* __restrict__ edg) {
    int i = (blockIdx.x * blockDim.x + threadIdx.x) * 4;
    if (i >= NNZE) return;
    int4 e4 = *(const int4*)&edg[i];
    int4 v4 = *(const int4*)&vtx[i];
    int p0 = atomicAdd(&g_cur_e[e4.x], 1);
    int p1 = atomicAdd(&g_cur_e[e4.y], 1);
    int p2 = atomicAdd(&g_cur_e[e4.z], 1);
    int p3 = atomicAdd(&g_cur_e[e4.w], 1);
    g_adj_e[p0] = v4.x;
    g_adj_e[p1] = v4.y;
    g_adj_e[p2] = v4.z;
    g_adj_e[p3] = v4.w;
    int q0 = atomicAdd(&g_cur_v[v4.x], 1);
    int q1 = atomicAdd(&g_cur_v[v4.y], 1);
    int q2 = atomicAdd(&g_cur_v[v4.z], 1);
    int q3 = atomicAdd(&g_cur_v[v4.w], 1);
    g_adj_v[q0] = e4.x;
    g_adj_v[q1] = e4.y;
    g_adj_v[q2] = e4.z;
    g_adj_v[q3] = e4.w;
}

// -------- weight prep (all 5 slots in one launch, grid.y = slot) --------
__global__ void k_prep_frag(const float* __restrict__ W0, const float* __restrict__ Ws) {
    int slot = blockIdx.y;
    int idx = blockIdx.x * blockDim.x + threadIdx.x;
    if (idx >= HD * HD) return;
    const float* W = (slot == 0) ? W0 : Ws + (slot - 1) * HD * HD;
    int k = idx >> 7, n = idx & 127;
    float w = W[idx];
    if (slot > 0) {
        float beta = logf(0.5f / (float)slot + 1.0f);
        w = beta * w;
        if (k == n) w += (1.0f - beta);
    }
    __nv_bfloat16 hi, lo;
    bsplit(w, hi, lo);
    int kt = k >> 4, kc = k & 15;
    int nt = n >> 3, nc = n & 7;
    int lane = nc * 4 + ((kc & 7) >> 1);
    int elem = ((kt * 16 + nt) * 32 + lane) * 4 + ((kc >> 3) << 1) + (kc & 1);
    g_Bhi[slot * HD * HD + elem] = hi;
    g_Blo[slot * HD * HD + elem] = lo;
}

// -------- aggregation: warp per segment, fp16x2 rows (256B/row) ---------
__global__ __launch_bounds__(256) void k_edge_agg() {
    int e = (blockIdx.x * blockDim.x + threadIdx.x) >> 5;
    if (e >= ME) return;
    int lane = threadIdx.x & 31;
    const uint2* __restrict__ hb = (const uint2*)g_hb;   // index: v*32 + lane
    int beg = g_off_e[e], end = g_off_e[e + 1];
    float4 acc = make_float4(0.f, 0.f, 0.f, 0.f);
    int p = beg;
    for (; p + 4 <= end; p += 4) {
        int v0 = g_adj_e[p], v1 = g_adj_e[p + 1], v2 = g_adj_e[p + 2], v3 = g_adj_e[p + 3];
        uint2 u0 = hb[v0 * 32 + lane];
        uint2 u1 = hb[v1 * 32 + lane];
        uint2 u2 = hb[v2 * 32 + lane];
        uint2 u3 = hb[v3 * 32 + lane];
        float4 a = h4f(u0), b = h4f(u1), c = h4f(u2), d = h4f(u3);
        acc.x += a.x + b.x + c.x + d.x;
        acc.y += a.y + b.y + c.y + d.y;
        acc.z += a.z + b.z + c.z + d.z;
        acc.w += a.w + b.w + c.w + d.w;
    }
    for (; p < end; p++) {
        float4 a = h4f(hb[g_adj_e[p] * 32 + lane]);
        acc.x += a.x; acc.y += a.y; acc.z += a.z; acc.w += a.w;
    }
    float inv = 1.0f / (float)max(end - beg, 1);
    acc.x *= inv; acc.y *= inv; acc.z *= inv; acc.w *= inv;
    ((uint2*)g_Xeb)[e * 32 + lane] = f4h(acc);
}

// vertex agg fused with L2-normalize + alpha blend; writes fp32 Xi.
// division by cnt_v cancels under L2 normalization.
__global__ __launch_bounds__(256) void k_vert_agg() {
    int v = (blockIdx.x * blockDim.x + threadIdx.x) >> 5;
    if (v >= NV) return;
    int lane = threadIdx.x & 31;
    const uint2* __restrict__ xe = (const uint2*)g_Xeb;
    int beg = g_off_v[v], end = g_off_v[v + 1];
    float4 acc = make_float4(0.f, 0.f, 0.f, 0.f);
    int p = beg;
    for (; p + 4 <= end; p += 4) {
        int e0 = g_adj_v[p], e1 = g_adj_v[p + 1], e2 = g_adj_v[p + 2], e3 = g_adj_v[p + 3];
        uint2 u0 = xe[e0 * 32 + lane];
        uint2 u1 = xe[e1 * 32 + lane];
        uint2 u2 = xe[e2 * 32 + lane];
        uint2 u3 = xe[e3 * 32 + lane];
        float4 a = h4f(u0), b = h4f(u1), c = h4f(u2), d = h4f(u3);
        acc.x += a.x + b.x + c.x + d.x;
        acc.y += a.y + b.y + c.y + d.y;
        acc.z += a.z + b.z + c.z + d.z;
        acc.w += a.w + b.w + c.w + d.w;
    }
    for (; p < end; p++) {
        float4 a = h4f(xe[g_adj_v[p] * 32 + lane]);
        acc.x += a.x; acc.y += a.y; acc.z += a.z; acc.w += a.w;
    }
    float ss = acc.x * acc.x + acc.y * acc.y + acc.z * acc.z + acc.w * acc.w;
    #pragma unroll
    for (int o = 16; o > 0; o >>= 1) ss += __shfl_xor_sync(0xffffffffu, ss, o);
    float s9 = (ss > 0.f) ? (0.9f / sqrtf(ss)) : 0.f;
    float4 x0 = h4f(((const uint2*)g_h0b)[v * 32 + lane]);
    float4 o;
    o.x = acc.x * s9 + 0.1f * x0.x;
    o.y = acc.y * s9 + 0.1f * x0.y;
    o.z = acc.z * s9 + 0.1f * x0.z;
    o.w = acc.w * s9 + 0.1f * x0.w;
    *(float4*)&g_Xi[v * HD + lane * 4] = o;
}

// ---- MMA GEMM: h_fp16 = relu(A[M,128] @ W_slot (+bias)), opt dual h0 ----
#define GB_SMEM (4 * 8192 * 4)

template <bool BIAS, bool DUAL>
__global__ __launch_bounds__(256, 1) void gemm_mma(
    const float* __restrict__ A, int slot, const float* __restrict__ bias,
    int Mrows)
{
    extern __shared__ uint32_t dyn[];
    uint32_t* sAhi = dyn;
    uint32_t* sAlo = dyn + 8192;
    uint32_t* sBhi = dyn + 16384;
    uint32_t* sBlo = dyn + 24576;

    int tid = threadIdx.x;
    int m0 = blockIdx.x * 128;

    // stage B: straight copy of pre-split frag-layout weights
    {
        const uint4* srcH = (const uint4*)(g_Bhi + slot * HD * HD);
        const uint4* srcL = (const uint4*)(g_Blo + slot * HD * HD);
        uint4* dstH = (uint4*)sBhi;
        uint4* dstL = (uint4*)sBlo;
        #pragma unroll
        for (int it = 0; it < 8; it++) {
            dstH[tid + it * 256] = srcH[tid + it * 256];
            dstL[tid + it * 256] = srcL[tid + it * 256];
        }
    }
    // stage A: coalesced fp32 read, split, frag-layout bf16 write
    {
        #pragma unroll
        for (int it = 0; it < 32; it++) {
            int idx2 = tid + it * 256;
            int m = idx2 >> 6;
            int k = (idx2 & 63) * 2;
            int gm = min(m0 + m, Mrows - 1);
            float2 a = *(const float2*)&A[gm * HD + k];
            __nv_bfloat16 h0b, l0b, h1b, l1b;
            bsplit(a.x, h0b, l0b);
            bsplit(a.y, h1b, l1b);
            int kt = k >> 4, kc = k & 15;
            int mt = m >> 4, r = m & 15;
            int lane = (r & 7) * 4 + ((kc & 7) >> 1);
            int reg = (r >> 3) + ((kc >> 3) << 1);
            int w32 = (((kt * 8 + mt) * 32 + lane) << 2) + reg;
            __nv_bfloat162 ph, pl;
            ph.x = h0b; ph.y = h1b;
            pl.x = l0b; pl.y = l1b;
            sAhi[w32] = *(uint32_t*)&ph;
            sAlo[w32] = *(uint32_t*)&pl;
        }
    }
    __syncthreads();

    int wid = tid >> 5;
    int lane = tid & 31;
    int mwarp = wid & 3;
    int nwarp = wid >> 2;
    int mt0 = mwarp * 2;
    int nt0 = nwarp * 8;

    float acc[2][8][4];
    #pragma unroll
    for (int i = 0; i < 2; i++)
        #pragma unroll
        for (int j = 0; j < 8; j++)
            #pragma unroll
            for (int q = 0; q < 4; q++) acc[i][j][q] = 0.f;

    #pragma unroll 1
    for (int seg = 0; seg < 3; seg++) {
        const uint4* aBuf = (const uint4*)(seg == 1 ? sAlo : sAhi);
        const uint2* bBuf = (const uint2*)(seg == 2 ? sBlo : sBhi);
        #pragma unroll 1
        for (int kt = 0; kt < 8; kt++) {
            uint4 afr[2];
            afr[0] = aBuf[(kt * 8 + mt0) * 32 + lane];
            afr[1] = aBuf[(kt * 8 + mt0 + 1) * 32 + lane];
            uint2 bfr[8];
            #pragma unroll
            for (int j = 0; j < 8; j++)
                bfr[j] = bBuf[(kt * 16 + nt0 + j) * 32 + lane];
            #pragma unroll
            for (int i = 0; i < 2; i++)
                #pragma unroll
                for (int j = 0; j < 8; j++)
                    mma16816(acc[i][j], afr[i], bfr[j]);
        }
    }

    // epilogue: bias + relu + fp16x2 store (dual -> h0)
    int rbase = m0 + mwarp * 32 + (lane >> 2);
    int cbase = nwarp * 64 + (lane & 3) * 2;
    #pragma unroll
    for (int i = 0; i < 2; i++) {
        #pragma unroll
        for (int j = 0; j < 8; j++) {
            int col = cbase + j * 8;
            float bx = BIAS ? bias[col] : 0.f;
            float by = BIAS ? bias[col + 1] : 0.f;
            int r0 = rbase + i * 16;
            if (r0 < Mrows) {
                __half2 pb = __floats2half2_rn(
                    fmaxf(acc[i][j][0] + bx, 0.f), fmaxf(acc[i][j][1] + by, 0.f));
                g_hb[r0 * 64 + (col >> 1)] = pb;
                if (DUAL) g_h0b[r0 * 64 + (col >> 1)] = pb;
            }
            int r1 = rbase + i * 16 + 8;
            if (r1 < Mrows) {
                __half2 pb = __floats2half2_rn(
                    fmaxf(acc[i][j][2] + bx, 0.f), fmaxf(acc[i][j][3] + by, 0.f));
                g_hb[r1 * 64 + (col >> 1)] = pb;
                if (DUAL) g_h0b[r1 * 64 + (col >> 1)] = pb;
            }
        }
    }
}

// -------- output GEMM: fp16 h [M,128] @ W[128,40] + bias ------------------
__global__ __launch_bounds__(320) void gemm_out(
    const float* __restrict__ W, const float* __restrict__ bias,
    float* __restrict__ C, int Mrows)
{
    __shared__ float xs[128][33];
    __shared__ float ws[128][40];
    int tid = threadIdx.x;
    int m0 = blockIdx.x * 128;

    for (int idx = tid; idx < 128 * 40; idx += 320)
        ws[idx / 40][idx % 40] = W[idx];

    int slot = tid / 5;
    int cg = tid % 5;
    int r0 = slot, r1 = slot + 64;

    u64 acc[2][4];
    #pragma unroll
    for (int r = 0; r < 2; r++)
        #pragma unroll
        for (int j = 0; j < 4; j++) acc[r][j] = 0ull;

    for (int kc = 0; kc < HD; kc += 32) {
        __syncthreads();
        for (int idx = tid; idx < 128 * 16; idx += 320) {
            int r = idx >> 4, kp = idx & 15;
            int m = min(m0 + r, Mrows - 1);
            __half2 p = g_hb[m * 64 + (kc >> 1) + kp];
            float2 f = __half22float2(p);
            xs[r][kp * 2] = f.x;
            xs[r][kp * 2 + 1] = f.y;
        }
        __syncthreads();
        #pragma unroll
        for (int k = 0; k < 32; k++) {
            u64 aa0 = bcast2(xs[r0][k]);
            u64 aa1 = bcast2(xs[r1][k]);
            ulonglong2 wp0 = *(const ulonglong2*)&ws[kc + k][cg * 8];
            ulonglong2 wp1 = *(const ulonglong2*)&ws[kc + k][cg * 8 + 4];
            ffma2(acc[0][0], aa0, wp0.x, acc[0][0]);
            ffma2(acc[0][1], aa0, wp0.y, acc[0][1]);
            ffma2(acc[0][2], aa0, wp1.x, acc[0][2]);
            ffma2(acc[0][3], aa0, wp1.y, acc[0][3]);
            ffma2(acc[1][0], aa1, wp0.x, acc[1][0]);
            ffma2(acc[1][1], aa1, wp0.y, acc[1][1]);
            ffma2(acc[1][2], aa1, wp1.x, acc[1][2]);
            ffma2(acc[1][3], aa1, wp1.y, acc[1][3]);
        }
    }

    #pragma unroll
    for (int r = 0; r < 2; r++) {
        int m = m0 + (r ? r1 : r0);
        if (m < Mrows) {
            float v[8];
            #pragma unroll
            for (int j2 = 0; j2 < 4; j2++) {
                float2 f = unpack2(acc[r][j2]);
                v[j2 * 2 + 0] = f.x + bias[cg * 8 + j2 * 2 + 0];
                v[j2 * 2 + 1] = f.y + bias[cg * 8 + j2 * 2 + 1];
            }
            float4* dst = (float4*)&C[m * NCLS + cg * 8];
            dst[0] = *(float4*)&v[0];
            dst[1] = *(float4*)&v[4];
        }
    }
}

// ---------------------------------------------------------------------
extern "C" void kernel_launch(void* const* d_in, const int* in_sizes, int n_in,
                              void* d_out, int out_size) {
    const float* x    = (const float*)d_in[0];
    const float* W0   = (const float*)d_in[1];
    const float* b0   = (const float*)d_in[2];
    const float* Ws   = (const float*)d_in[3];
    const float* Wout = (const float*)d_in[4];
    const float* bout = (const float*)d_in[5];
    const int* vtx    = (const int*)d_in[6];
    const int* edg    = (const int*)d_in[7];
    float* out = (float*)d_out;

    float* Xi;
    cudaGetSymbolAddress((void**)&Xi, g_Xi);

    cudaFuncSetAttribute(gemm_mma<true, true>,
                         cudaFuncAttributeMaxDynamicSharedMemorySize, GB_SMEM);
    cudaFuncSetAttribute(gemm_mma<false, false>,
                         cudaFuncAttributeMaxDynamicSharedMemorySize, GB_SMEM);

    const int gemmBlocks = (NV + 127) / 128;

    // CSR build
    k_zero_counts<<<(ME + NV + 255) / 256, 256>>>();
    k_count4<<<(NNZE / 4 + 255) / 256, 256>>>(vtx, edg);
    k_scan<<<2, 1024>>>();
    k_fill4<<<(NNZE / 4 + 255) / 256, 256>>>(vtx, edg);

    // weight prep: all 5 slots in one launch
    k_prep_frag<<<dim3((HD * HD + 255) / 256, 5), 256>>>(W0, Ws);

    // h = h0 = relu(x @ W0 + b0)  (fp16 stores)
    gemm_mma<true, true><<<gemmBlocks, 256, GB_SMEM>>>(x, 0, b0, NV);

    for (int i = 0; i < DEPTH; i++) {
        k_edge_agg<<<(ME * 32 + 255) / 256, 256>>>();
        k_vert_agg<<<(NV * 32 + 255) / 256, 256>>>();
        // h = relu(Xi @ ((1-b)I + b*Ws[i]))
        gemm_mma<false, false><<<gemmBlocks, 256, GB_SMEM>>>(Xi, i + 1, nullptr, NV);
    }

    gemm_out<<<gemmBlocks, 320>>>(Wout, bout, out, NV);
}

// round 7
// speedup vs baseline: 1.0286x; 1.0286x over previous
#include <cuda_runtime.h>
#include <cuda_bf16.h>
#include <cstdint>
#include <math.h>

#define NV   100000
#define ME   50000
#define NNZE 800000
#define HD   128
#define NCLS 40
#define DEPTH 4

typedef unsigned long long u64;

// -------- scratch (no allocations allowed; __device__ globals) --------
__device__ float g_h [NV * HD];     // current features x
__device__ float g_h0[NV * HD];     // x0 (post first relu)
__device__ float g_Xi[NV * HD];     // blended GEMM input
__device__ float g_Xe[ME * HD];     // edge features
// weights pre-split to bf16 hi/lo in MMA fragment layout. slot0=W0, 1..4=folded
__device__ __align__(16) __nv_bfloat16 g_Bhi[5 * HD * HD];
__device__ __align__(16) __nv_bfloat16 g_Blo[5 * HD * HD];
__device__ int g_cnt_e[ME], g_cnt_v[NV];
__device__ int g_off_e[ME + 1], g_off_v[NV + 1];
__device__ int g_cur_e[ME], g_cur_v[NV];
__device__ int g_adj_e[NNZE];   // vertex ids grouped by edge
__device__ int g_adj_v[NNZE];   // edge ids grouped by vertex

// -------- f32x2 helpers (used by gemm_out) -----------------------------
__device__ __forceinline__ void ffma2(u64& d, u64 a, u64 b, u64 c) {
    asm("fma.rn.f32x2 %0, %1, %2, %3;" : "=l"(d) : "l"(a), "l"(b), "l"(c));
}
__device__ __forceinline__ u64 bcast2(float a) {
    u64 r;
    asm("mov.b64 %0, {%1, %1};" : "=l"(r) : "f"(a));
    return r;
}
__device__ __forceinline__ float2 unpack2(u64 u) {
    float2 f;
    asm("mov.b64 {%0, %1}, %2;" : "=f"(f.x), "=f"(f.y) : "l"(u));
    return f;
}

// -------- bf16 split helpers -------------------------------------------
__device__ __forceinline__ void bsplit(float a, __nv_bfloat16& hi, __nv_bfloat16& lo) {
    hi = __float2bfloat16_rn(a);
    lo = __float2bfloat16_rn(a - __bfloat162float(hi));
}

// mma.sync m16n8k16 bf16 -> f32 accum
__device__ __forceinline__ void mma16816(float* d, const uint4& a, const uint2& b) {
    asm volatile(
        "mma.sync.aligned.m16n8k16.row.col.f32.bf16.bf16.f32 "
        "{%0,%1,%2,%3}, {%4,%5,%6,%7}, {%8,%9}, {%0,%1,%2,%3};"
        : "+f"(d[0]), "+f"(d[1]), "+f"(d[2]), "+f"(d[3])
        : "r"(a.x), "r"(a.y), "r"(a.z), "r"(a.w), "r"(b.x), "r"(b.y));
}

// ---------------------------------------------------------------------
__global__ void k_zero_counts() {
    int i = blockIdx.x * blockDim.x + threadIdx.x;
    if (i < ME) g_cnt_e[i] = 0;
    if (i < NV) g_cnt_v[i] = 0;
}

__global__ void k_count(const int* __restrict__ vtx, const int* __restrict__ edg) {
    int i = blockIdx.x * blockDim.x + threadIdx.x;
    if (i >= NNZE) return;
    atomicAdd(&g_cnt_e[edg[i]], 1);
    atomicAdd(&g_cnt_v[vtx[i]], 1);
}

__global__ void k_scan() {
    const int which = blockIdx.x;
    const int len = which ? NV : ME;
    const int* cnt = which ? g_cnt_v : g_cnt_e;
    int* off = which ? g_off_v : g_off_e;
    int* cur = which ? g_cur_v : g_cur_e;

    __shared__ int sm[1024];
    int t = threadIdx.x;
    int chunk = (len + 1023) >> 10;
    int lo = t * chunk;
    int hi = min(lo + chunk, len);

    int s = 0;
    for (int i = lo; i < hi; i++) s += cnt[i];
    sm[t] = s;
    __syncthreads();
    for (int o = 1; o < 1024; o <<= 1) {
        int add = (t >= o) ? sm[t - o] : 0;
        __syncthreads();
        sm[t] += add;
        __syncthreads();
    }
    int excl = sm[t] - s;
    int run = excl;
    for (int i = lo; i < hi; i++) {
        off[i] = run;
        cur[i] = run;
        run += cnt[i];
    }
    if (t == 1023) off[len] = run;
}

__global__ void k_fill(const int* __restrict__ vtx, const int* __restrict__ edg) {
    int i = blockIdx.x * blockDim.x + threadIdx.x;
    if (i >= NNZE) return;
    int e = edg[i], v = vtx[i];
    int pe = atomicAdd(&g_cur_e[e], 1);
    g_adj_e[pe] = v;
    int pv = atomicAdd(&g_cur_v[v], 1);
    g_adj_v[pv] = e;
}

// -------- weight prep (all 5 slots in one launch, grid.y = slot) --------
// B frag (m16n8k16 col operand): (k,n) of 16x8 tile ->
//   lane=(n&7)*4+((k&7)>>1), elem=((kt*16+nt)*32+lane)*4 + ((k>>3)&1)*2 + (k&1)
__global__ void k_prep_frag(const float* __restrict__ W0, const float* __restrict__ Ws) {
    int slot = blockIdx.y;
    int idx = blockIdx.x * blockDim.x + threadIdx.x;
    if (idx >= HD * HD) return;
    const float* W = (slot == 0) ? W0 : Ws + (slot - 1) * HD * HD;
    int k = idx >> 7, n = idx & 127;
    float w = W[idx];
    if (slot > 0) {
        float beta = logf(0.5f / (float)slot + 1.0f);
        w = beta * w;
        if (k == n) w += (1.0f - beta);
    }
    __nv_bfloat16 hi, lo;
    bsplit(w, hi, lo);
    int kt = k >> 4, kc = k & 15;
    int nt = n >> 3, nc = n & 7;
    int lane = nc * 4 + ((kc & 7) >> 1);
    int elem = ((kt * 16 + nt) * 32 + lane) * 4 + ((kc >> 3) << 1) + (kc & 1);
    g_Bhi[slot * HD * HD + elem] = hi;
    g_Blo[slot * HD * HD + elem] = lo;
}

// -------- aggregation: warp per segment, gather-only (fp32) -------------
__global__ __launch_bounds__(256) void k_edge_agg() {
    int e = (blockIdx.x * blockDim.x + threadIdx.x) >> 5;
    if (e >= ME) return;
    int lane = threadIdx.x & 31;
    int beg = g_off_e[e], end = g_off_e[e + 1];
    float4 acc = make_float4(0.f, 0.f, 0.f, 0.f);
    int p = beg;
    for (; p + 4 <= end; p += 4) {
        int v0 = g_adj_e[p], v1 = g_adj_e[p + 1], v2 = g_adj_e[p + 2], v3 = g_adj_e[p + 3];
        float4 a = *(const float4*)&g_h[v0 * HD + lane * 4];
        float4 b = *(const float4*)&g_h[v1 * HD + lane * 4];
        float4 c = *(const float4*)&g_h[v2 * HD + lane * 4];
        float4 d = *(const float4*)&g_h[v3 * HD + lane * 4];
        acc.x += a.x + b.x + c.x + d.x;
        acc.y += a.y + b.y + c.y + d.y;
        acc.z += a.z + b.z + c.z + d.z;
        acc.w += a.w + b.w + c.w + d.w;
    }
    for (; p < end; p++) {
        int v = g_adj_e[p];
        float4 a = *(const float4*)&g_h[v * HD + lane * 4];
        acc.x += a.x; acc.y += a.y; acc.z += a.z; acc.w += a.w;
    }
    float inv = 1.0f / (float)max(end - beg, 1);
    acc.x *= inv; acc.y *= inv; acc.z *= inv; acc.w *= inv;
    *(float4*)&g_Xe[e * HD + lane * 4] = acc;
}

// vertex agg fused with L2-normalize + alpha blend.
// division by cnt_v cancels under L2 normalization.
__global__ __launch_bounds__(256) void k_vert_agg() {
    int v = (blockIdx.x * blockDim.x + threadIdx.x) >> 5;
    if (v >= NV) return;
    int lane = threadIdx.x & 31;
    int beg = g_off_v[v], end = g_off_v[v + 1];
    float4 acc = make_float4(0.f, 0.f, 0.f, 0.f);
    int p = beg;
    for (; p + 4 <= end; p += 4) {
        int e0 = g_adj_v[p], e1 = g_adj_v[p + 1], e2 = g_adj_v[p + 2], e3 = g_adj_v[p + 3];
        float4 a = *(const float4*)&g_Xe[e0 * HD + lane * 4];
        float4 b = *(const float4*)&g_Xe[e1 * HD + lane * 4];
        float4 c = *(const float4*)&g_Xe[e2 * HD + lane * 4];
        float4 d = *(const float4*)&g_Xe[e3 * HD + lane * 4];
        acc.x += a.x + b.x + c.x + d.x;
        acc.y += a.y + b.y + c.y + d.y;
        acc.z += a.z + b.z + c.z + d.z;
        acc.w += a.w + b.w + c.w + d.w;
    }
    for (; p < end; p++) {
        int e = g_adj_v[p];
        float4 a = *(const float4*)&g_Xe[e * HD + lane * 4];
        acc.x += a.x; acc.y += a.y; acc.z += a.z; acc.w += a.w;
    }
    float ss = acc.x * acc.x + acc.y * acc.y + acc.z * acc.z + acc.w * acc.w;
    #pragma unroll
    for (int o = 16; o > 0; o >>= 1) ss += __shfl_xor_sync(0xffffffffu, ss, o);
    float s9 = (ss > 0.f) ? (0.9f / sqrtf(ss)) : 0.f;
    float4 x0 = *(const float4*)&g_h0[v * HD + lane * 4];
    float4 o;
    o.x = acc.x * s9 + 0.1f * x0.x;
    o.y = acc.y * s9 + 0.1f * x0.y;
    o.z = acc.z * s9 + 0.1f * x0.z;
    o.w = acc.w * s9 + 0.1f * x0.w;
    *(float4*)&g_Xi[v * HD + lane * 4] = o;
}

// ---- MMA GEMM: C[M,128] = relu(A[M,128] @ W[128,128] (+bias)) ----------
// bf16 2-term split, 3 products. K processed in two 64-wide halves so smem
// is 64KB -> 2 CTAs/SM: one CTA's staging overlaps the other's HMMA.
// SMEM (u32 units): sAhi[4096] sAlo[4096] sBhi[4096] sBlo[4096] = 64KB
#define GB_SMEM (4 * 4096 * 4)

template <bool BIAS, bool DUAL>
__global__ __launch_bounds__(256, 2) void gemm_mma(
    const float* __restrict__ A, int slot, const float* __restrict__ bias,
    float* __restrict__ C, float* __restrict__ C2, int Mrows)
{
    extern __shared__ uint32_t dyn[];
    uint32_t* sAhi = dyn;
    uint32_t* sAlo = dyn + 4096;
    uint32_t* sBhi = dyn + 8192;
    uint32_t* sBlo = dyn + 12288;

    int tid = threadIdx.x;
    int m0 = blockIdx.x * 128;
    int wid = tid >> 5;
    int lane = tid & 31;
    int mwarp = wid & 3;
    int nwarp = wid >> 2;
    int mt0 = mwarp * 2;
    int nt0 = nwarp * 8;

    float acc[2][8][4];
    #pragma unroll
    for (int i = 0; i < 2; i++)
        #pragma unroll
        for (int j = 0; j < 8; j++)
            #pragma unroll
            for (int q = 0; q < 4; q++) acc[i][j][q] = 0.f;

    #pragma unroll 1
    for (int h = 0; h < 2; h++) {
        if (h) __syncthreads();   // protect smem reuse between halves
        // stage B half: contiguous copy of pre-split frag-layout weights
        {
            const uint4* srcH = (const uint4*)(g_Bhi + slot * HD * HD + h * 8192);
            const uint4* srcL = (const uint4*)(g_Blo + slot * HD * HD + h * 8192);
            uint4* dstH = (uint4*)sBhi;
            uint4* dstL = (uint4*)sBlo;
            #pragma unroll
            for (int it = 0; it < 4; it++) {
                dstH[tid + it * 256] = srcH[tid + it * 256];
                dstL[tid + it * 256] = srcL[tid + it * 256];
            }
        }
        // stage A half [128 x 64]: coalesced fp32 read, split, frag write
        {
            #pragma unroll
            for (int it = 0; it < 16; it++) {
                int idx2 = tid + it * 256;            // float2 index in half
                int m = idx2 >> 5;                    // 0..127
                int kl = (idx2 & 31) * 2;             // local even k 0..62
                int gm = min(m0 + m, Mrows - 1);
                float2 a = *(const float2*)&A[gm * HD + h * 64 + kl];
                __nv_bfloat16 h0b, l0b, h1b, l1b;
                bsplit(a.x, h0b, l0b);
                bsplit(a.y, h1b, l1b);
                int ktl = kl >> 4, kc = kl & 15;
                int mt = m >> 4, r = m & 15;
                int flane = (r & 7) * 4 + ((kc & 7) >> 1);
                int reg = (r >> 3) + ((kc >> 3) << 1);
                int w32 = (((ktl * 8 + mt) * 32 + flane) << 2) + reg;
                __nv_bfloat162 ph, pl;
                ph.x = h0b; ph.y = h1b;
                pl.x = l0b; pl.y = l1b;
                sAhi[w32] = *(uint32_t*)&ph;
                sAlo[w32] = *(uint32_t*)&pl;
            }
        }
        __syncthreads();

        #pragma unroll 1
        for (int seg = 0; seg < 3; seg++) {
            const uint4* aBuf = (const uint4*)(seg == 1 ? sAlo : sAhi);
            const uint2* bBuf = (const uint2*)(seg == 2 ? sBlo : sBhi);
            #pragma unroll 1
            for (int ktl = 0; ktl < 4; ktl++) {
                uint4 afr[2];
                afr[0] = aBuf[(ktl * 8 + mt0) * 32 + lane];
                afr[1] = aBuf[(ktl * 8 + mt0 + 1) * 32 + lane];
                uint2 bfr[8];
                #pragma unroll
                for (int j = 0; j < 8; j++)
                    bfr[j] = bBuf[(ktl * 16 + nt0 + j) * 32 + lane];
                #pragma unroll
                for (int i = 0; i < 2; i++)
                    #pragma unroll
                    for (int j = 0; j < 8; j++)
                        mma16816(acc[i][j], afr[i], bfr[j]);
            }
        }
    }

    // epilogue: bias + relu + store (dual)
    int rbase = m0 + mwarp * 32 + (lane >> 2);
    int cbase = nwarp * 64 + (lane & 3) * 2;
    #pragma unroll
    for (int i = 0; i < 2; i++) {
        #pragma unroll
        for (int j = 0; j < 8; j++) {
            int col = cbase + j * 8;
            float bx = BIAS ? bias[col] : 0.f;
            float by = BIAS ? bias[col + 1] : 0.f;
            int r0 = rbase + i * 16;
            if (r0 < Mrows) {
                float2 v;
                v.x = fmaxf(acc[i][j][0] + bx, 0.f);
                v.y = fmaxf(acc[i][j][1] + by, 0.f);
                *(float2*)&C[r0 * HD + col] = v;
                if (DUAL) *(float2*)&C2[r0 * HD + col] = v;
            }
            int r1 = rbase + i * 16 + 8;
            if (r1 < Mrows) {
                float2 v;
                v.x = fmaxf(acc[i][j][2] + bx, 0.f);
                v.y = fmaxf(acc[i][j][3] + by, 0.f);
                *(float2*)&C[r1 * HD + col] = v;
                if (DUAL) *(float2*)&C2[r1 * HD + col] = v;
            }
        }
    }
}

// -------- output GEMM: [M,128] @ [128,40] + bias (f32x2 inner) ------------
__global__ __launch_bounds__(320) void gemm_out(
    const float* __restrict__ A, const float* __restrict__ W,
    const float* __restrict__ bias, float* __restrict__ C, int Mrows)
{
    __shared__ float xs[128][33];
    __shared__ float ws[128][40];
    int tid = threadIdx.x;
    int m0 = blockIdx.x * 128;

    for (int idx = tid; idx < 128 * 40; idx += 320)
        ws[idx / 40][idx % 40] = W[idx];

    int slot = tid / 5;
    int cg = tid % 5;
    int r0 = slot, r1 = slot + 64;

    u64 acc[2][4];
    #pragma unroll
    for (int r = 0; r < 2; r++)
        #pragma unroll
        for (int j = 0; j < 4; j++) acc[r][j] = 0ull;

    for (int kc = 0; kc < HD; kc += 32) {
        __syncthreads();
        for (int idx = tid; idx < 128 * 32; idx += 320) {
            int r = idx >> 5, k = idx & 31;
            int m = min(m0 + r, Mrows - 1);
            xs[r][k] = A[m * HD + kc + k];
        }
        __syncthreads();
        #pragma unroll
        for (int k = 0; k < 32; k++) {
            u64 aa0 = bcast2(xs[r0][k]);
            u64 aa1 = bcast2(xs[r1][k]);
            ulonglong2 wp0 = *(const ulonglong2*)&ws[kc + k][cg * 8];
            ulonglong2 wp1 = *(const ulonglong2*)&ws[kc + k][cg * 8 + 4];
            ffma2(acc[0][0], aa0, wp0.x, acc[0][0]);
            ffma2(acc[0][1], aa0, wp0.y, acc[0][1]);
            ffma2(acc[0][2], aa0, wp1.x, acc[0][2]);
            ffma2(acc[0][3], aa0, wp1.y, acc[0][3]);
            ffma2(acc[1][0], aa1, wp0.x, acc[1][0]);
            ffma2(acc[1][1], aa1, wp0.y, acc[1][1]);
            ffma2(acc[1][2], aa1, wp1.x, acc[1][2]);
            ffma2(acc[1][3], aa1, wp1.y, acc[1][3]);
        }
    }

    #pragma unroll
    for (int r = 0; r < 2; r++) {
        int m = m0 + (r ? r1 : r0);
        if (m < Mrows) {
            float v[8];
            #pragma unroll
            for (int j2 = 0; j2 < 4; j2++) {
                float2 f = unpack2(acc[r][j2]);
                v[j2 * 2 + 0] = f.x + bias[cg * 8 + j2 * 2 + 0];
                v[j2 * 2 + 1] = f.y + bias[cg * 8 + j2 * 2 + 1];
            }
            float4* dst = (float4*)&C[m * NCLS + cg * 8];
            dst[0] = *(float4*)&v[0];
            dst[1] = *(float4*)&v[4];
        }
    }
}

// ---------------------------------------------------------------------
extern "C" void kernel_launch(void* const* d_in, const int* in_sizes, int n_in,
                              void* d_out, int out_size) {
    const float* x    = (const float*)d_in[0];
    const float* W0   = (const float*)d_in[1];
    const float* b0   = (const float*)d_in[2];
    const float* Ws   = (const float*)d_in[3];
    const float* Wout = (const float*)d_in[4];
    const float* bout = (const float*)d_in[5];
    const int* vtx    = (const int*)d_in[6];
    const int* edg    = (const int*)d_in[7];
    float* out = (float*)d_out;

    float *h, *h0, *Xi;
    cudaGetSymbolAddress((void**)&h,  g_h);
    cudaGetSymbolAddress((void**)&h0, g_h0);
    cudaGetSymbolAddress((void**)&Xi, g_Xi);

    cudaFuncSetAttribute(gemm_mma<true, true>,
                         cudaFuncAttributeMaxDynamicSharedMemorySize, GB_SMEM);
    cudaFuncSetAttribute(gemm_mma<false, false>,
                         cudaFuncAttributeMaxDynamicSharedMemorySize, GB_SMEM);

    const int gemmBlocks = (NV + 127) / 128;

    // CSR build
    k_zero_counts<<<(ME + NV + 255) / 256, 256>>>();
    k_count<<<(NNZE + 255) / 256, 256>>>(vtx, edg);
    k_scan<<<2, 1024>>>();
    k_fill<<<(NNZE + 255) / 256, 256>>>(vtx, edg);

    // weight prep: all 5 slots in one launch
    k_prep_frag<<<dim3((HD * HD + 255) / 256, 5), 256>>>(W0, Ws);

    // h = h0 = relu(x @ W0 + b0)
    gemm_mma<true, true><<<gemmBlocks, 256, GB_SMEM>>>(x, 0, b0, h, h0, NV);

    for (int i = 0; i < DEPTH; i++) {
        k_edge_agg<<<(ME * 32 + 255) / 256, 256>>>();
        k_vert_agg<<<(NV * 32 + 255) / 256, 256>>>();
        // h = relu(Xi @ ((1-b)I + b*Ws[i]))
        gemm_mma<false, false><<<gemmBlocks, 256, GB_SMEM>>>(Xi, i + 1, nullptr,
                                                            h, nullptr, NV);
    }

    gemm_out<<<gemmBlocks, 320>>>(h, Wout, bout, out, NV);
}

// round 8
// speedup vs baseline: 1.4113x; 1.3721x over previous
#include <cuda_runtime.h>
#include <cuda_bf16.h>
#include <cstdint>
#include <math.h>

#define NV   100000
#define ME   50000
#define NNZE 800000
#define HD   128
#define NCLS 40
#define DEPTH 4

typedef unsigned long long u64;

// -------- scratch (no allocations allowed; __device__ globals) --------
__device__ float g_h [NV * HD];     // current features x
__device__ float g_h0[NV * HD];     // x0 (post first relu)
__device__ float g_Xi[NV * HD];     // blended GEMM input
__device__ float g_Xe[ME * HD];     // edge features
// weights pre-split to bf16 hi/lo in MMA fragment layout. slot0=W0, 1..4=folded
__device__ __align__(16) __nv_bfloat16 g_Bhi[5 * HD * HD];
__device__ __align__(16) __nv_bfloat16 g_Blo[5 * HD * HD];
__device__ int g_cnt_e[ME], g_cnt_v[NV];
__device__ int g_off_e[ME + 1], g_off_v[NV + 1];
__device__ int g_cur_e[ME], g_cur_v[NV];
__device__ int g_adj_e[NNZE];   // vertex ids grouped by edge
__device__ int g_adj_v[NNZE];   // edge ids grouped by vertex

// -------- f32x2 helpers (used by gemm_out) -----------------------------
__device__ __forceinline__ void ffma2(u64& d, u64 a, u64 b, u64 c) {
    asm("fma.rn.f32x2 %0, %1, %2, %3;" : "=l"(d) : "l"(a), "l"(b), "l"(c));
}
__device__ __forceinline__ u64 bcast2(float a) {
    u64 r;
    asm("mov.b64 %0, {%1, %1};" : "=l"(r) : "f"(a));
    return r;
}
__device__ __forceinline__ float2 unpack2(u64 u) {
    float2 f;
    asm("mov.b64 {%0, %1}, %2;" : "=f"(f.x), "=f"(f.y) : "l"(u));
    return f;
}

// -------- bf16 split helpers -------------------------------------------
__device__ __forceinline__ void bsplit(float a, __nv_bfloat16& hi, __nv_bfloat16& lo) {
    hi = __float2bfloat16_rn(a);
    lo = __float2bfloat16_rn(a - __bfloat162float(hi));
}

// mma.sync m16n8k16 bf16 -> f32 accum (baseline PTX, no arch suffix)
__device__ __forceinline__ void mma16816(float* d, const uint4& a, const uint2& b) {
    asm volatile(
        "mma.sync.aligned.m16n8k16.row.col.f32.bf16.bf16.f32 "
        "{%0,%1,%2,%3}, {%4,%5,%6,%7}, {%8,%9}, {%0,%1,%2,%3};"
        : "+f"(d[0]), "+f"(d[1]), "+f"(d[2]), "+f"(d[3])
        : "r"(a.x), "r"(a.y), "r"(a.z), "r"(a.w), "r"(b.x), "r"(b.y));
}

// ---------------------------------------------------------------------
__global__ void k_zero_counts() {
    int i = blockIdx.x * blockDim.x + threadIdx.x;
    if (i < ME) g_cnt_e[i] = 0;
    if (i < NV) g_cnt_v[i] = 0;
}

__global__ void k_count(const int* __restrict__ vtx, const int* __restrict__ edg) {
    int i = blockIdx.x * blockDim.x + threadIdx.x;
    if (i >= NNZE) return;
    atomicAdd(&g_cnt_e[edg[i]], 1);
    atomicAdd(&g_cnt_v[vtx[i]], 1);
}

__global__ void k_scan() {
    const int which = blockIdx.x;
    const int len = which ? NV : ME;
    const int* cnt = which ? g_cnt_v : g_cnt_e;
    int* off = which ? g_off_v : g_off_e;
    int* cur = which ? g_cur_v : g_cur_e;

    __shared__ int sm[1024];
    int t = threadIdx.x;
    int chunk = (len + 1023) >> 10;
    int lo = t * chunk;
    int hi = min(lo + chunk, len);

    int s = 0;
    for (int i = lo; i < hi; i++) s += cnt[i];
    sm[t] = s;
    __syncthreads();
    for (int o = 1; o < 1024; o <<= 1) {
        int add = (t >= o) ? sm[t - o] : 0;
        __syncthreads();
        sm[t] += add;
        __syncthreads();
    }
    int excl = sm[t] - s;
    int run = excl;
    for (int i = lo; i < hi; i++) {
        off[i] = run;
        cur[i] = run;
        run += cnt[i];
    }
    if (t == 1023) off[len] = run;
}

__global__ void k_fill(const int* __restrict__ vtx, const int* __restrict__ edg) {
    int i = blockIdx.x * blockDim.x + threadIdx.x;
    if (i >= NNZE) return;
    int e = edg[i], v = vtx[i];
    int pe = atomicAdd(&g_cur_e[e], 1);
    g_adj_e[pe] = v;
    int pv = atomicAdd(&g_cur_v[v], 1);
    g_adj_v[pv] = e;
}

// -------- weight prep (all 5 slots in one launch, grid.y = slot) --------
// B frag (m16n8k16 col operand): (k,n) of 16x8 tile ->
//   lane=(n&7)*4+((k&7)>>1), elem=((kt*16+nt)*32+lane)*4 + ((k>>3)&1)*2 + (k&1)
__global__ void k_prep_frag(const float* __restrict__ W0, const float* __restrict__ Ws) {
    int slot = blockIdx.y;
    int idx = blockIdx.x * blockDim.x + threadIdx.x;
    if (idx >= HD * HD) return;
    const float* W = (slot == 0) ? W0 : Ws + (slot - 1) * HD * HD;
    int k = idx >> 7, n = idx & 127;
    float w = W[idx];
    if (slot > 0) {
        float beta = logf(0.5f / (float)slot + 1.0f);
        w = beta * w;
        if (k == n) w += (1.0f - beta);
    }
    __nv_bfloat16 hi, lo;
    bsplit(w, hi, lo);
    int kt = k >> 4, kc = k & 15;
    int nt = n >> 3, nc = n & 7;
    int lane = nc * 4 + ((kc & 7) >> 1);
    int elem = ((kt * 16 + nt) * 32 + lane) * 4 + ((kc >> 3) << 1) + (kc & 1);
    g_Bhi[slot * HD * HD + elem] = hi;
    g_Blo[slot * HD * HD + elem] = lo;
}

// -------- aggregation: warp per segment, gather-only (fp32) -------------
__global__ __launch_bounds__(256) void k_edge_agg() {
    int e = (blockIdx.x * blockDim.x + threadIdx.x) >> 5;
    if (e >= ME) return;
    int lane = threadIdx.x & 31;
    int beg = g_off_e[e], end = g_off_e[e + 1];
    float4 acc = make_float4(0.f, 0.f, 0.f, 0.f);
    int p = beg;
    for (; p + 4 <= end; p += 4) {
        int v0 = g_adj_e[p], v1 = g_adj_e[p + 1], v2 = g_adj_e[p + 2], v3 = g_adj_e[p + 3];
        float4 a = *(const float4*)&g_h[v0 * HD + lane * 4];
        float4 b = *(const float4*)&g_h[v1 * HD + lane * 4];
        float4 c = *(const float4*)&g_h[v2 * HD + lane * 4];
        float4 d = *(const float4*)&g_h[v3 * HD + lane * 4];
        acc.x += a.x + b.x + c.x + d.x;
        acc.y += a.y + b.y + c.y + d.y;
        acc.z += a.z + b.z + c.z + d.z;
        acc.w += a.w + b.w + c.w + d.w;
    }
    for (; p < end; p++) {
        int v = g_adj_e[p];
        float4 a = *(const float4*)&g_h[v * HD + lane * 4];
        acc.x += a.x; acc.y += a.y; acc.z += a.z; acc.w += a.w;
    }
    float inv = 1.0f / (float)max(end - beg, 1);
    acc.x *= inv; acc.y *= inv; acc.z *= inv; acc.w *= inv;
    *(float4*)&g_Xe[e * HD + lane * 4] = acc;
}

// vertex agg fused with L2-normalize + alpha blend.
// division by cnt_v cancels under L2 normalization.
__global__ __launch_bounds__(256) void k_vert_agg() {
    int v = (blockIdx.x * blockDim.x + threadIdx.x) >> 5;
    if (v >= NV) return;
    int lane = threadIdx.x & 31;
    int beg = g_off_v[v], end = g_off_v[v + 1];
    float4 acc = make_float4(0.f, 0.f, 0.f, 0.f);
    int p = beg;
    for (; p + 4 <= end; p += 4) {
        int e0 = g_adj_v[p], e1 = g_adj_v[p + 1], e2 = g_adj_v[p + 2], e3 = g_adj_v[p + 3];
        float4 a = *(const float4*)&g_Xe[e0 * HD + lane * 4];
        float4 b = *(const float4*)&g_Xe[e1 * HD + lane * 4];
        float4 c = *(const float4*)&g_Xe[e2 * HD + lane * 4];
        float4 d = *(const float4*)&g_Xe[e3 * HD + lane * 4];
        acc.x += a.x + b.x + c.x + d.x;
        acc.y += a.y + b.y + c.y + d.y;
        acc.z += a.z + b.z + c.z + d.z;
        acc.w += a.w + b.w + c.w + d.w;
    }
    for (; p < end; p++) {
        int e = g_adj_v[p];
        float4 a = *(const float4*)&g_Xe[e * HD + lane * 4];
        acc.x += a.x; acc.y += a.y; acc.z += a.z; acc.w += a.w;
    }
    float ss = acc.x * acc.x + acc.y * acc.y + acc.z * acc.z + acc.w * acc.w;
    #pragma unroll
    for (int o = 16; o > 0; o >>= 1) ss += __shfl_xor_sync(0xffffffffu, ss, o);
    float s9 = (ss > 0.f) ? (0.9f / sqrtf(ss)) : 0.f;
    float4 x0 = *(const float4*)&g_h0[v * HD + lane * 4];
    float4 o;
    o.x = acc.x * s9 + 0.1f * x0.x;
    o.y = acc.y * s9 + 0.1f * x0.y;
    o.z = acc.z * s9 + 0.1f * x0.z;
    o.w = acc.w * s9 + 0.1f * x0.w;
    *(float4*)&g_Xi[v * HD + lane * 4] = o;
}

// ---- MMA GEMM: C[M,128] = relu(A[M,128] @ W[128,128] (+bias)) ----------
// bf16 2-term split, 3 products: Ahi*Bhi + Alo*Bhi + Ahi*Blo.
// EXACT R4 structure: one K=128 pass, 128KB smem, launch_bounds(256,1)
// (no min-blocks bound -> full register budget, no accumulator spills).
#define GB_SMEM (4 * 8192 * 4)

template <bool BIAS, bool DUAL>
__global__ __launch_bounds__(256, 1) void gemm_mma(
    const float* __restrict__ A, int slot, const float* __restrict__ bias,
    float* __restrict__ C, float* __restrict__ C2, int Mrows)
{
    extern __shared__ uint32_t dyn[];
    uint32_t* sAhi = dyn;
    uint32_t* sAlo = dyn + 8192;
    uint32_t* sBhi = dyn + 16384;
    uint32_t* sBlo = dyn + 24576;

    int tid = threadIdx.x;
    int m0 = blockIdx.x * 128;

    // stage B: straight copy of pre-split frag-layout weights
    {
        const uint4* srcH = (const uint4*)(g_Bhi + slot * HD * HD);
        const uint4* srcL = (const uint4*)(g_Blo + slot * HD * HD);
        uint4* dstH = (uint4*)sBhi;
        uint4* dstL = (uint4*)sBlo;
        #pragma unroll
        for (int it = 0; it < 8; it++) {
            dstH[tid + it * 256] = srcH[tid + it * 256];
            dstL[tid + it * 256] = srcL[tid + it * 256];
        }
    }
    // stage A: coalesced fp32 read, split, frag-layout bf16 write
    {
        #pragma unroll
        for (int it = 0; it < 32; it++) {
            int idx2 = tid + it * 256;            // float2 index
            int m = idx2 >> 6;                    // 0..127
            int k = (idx2 & 63) * 2;              // even k
            int gm = min(m0 + m, Mrows - 1);
            float2 a = *(const float2*)&A[gm * HD + k];
            __nv_bfloat16 h0b, l0b, h1b, l1b;
            bsplit(a.x, h0b, l0b);
            bsplit(a.y, h1b, l1b);
            int kt = k >> 4, kc = k & 15;
            int mt = m >> 4, r = m & 15;
            int lane = (r & 7) * 4 + ((kc & 7) >> 1);
            int reg = (r >> 3) + ((kc >> 3) << 1);
            int w32 = (((kt * 8 + mt) * 32 + lane) << 2) + reg;
            __nv_bfloat162 ph, pl;
            ph.x = h0b; ph.y = h1b;
            pl.x = l0b; pl.y = l1b;
            sAhi[w32] = *(uint32_t*)&ph;
            sAlo[w32] = *(uint32_t*)&pl;
        }
    }
    __syncthreads();

    // warp tiles: 4x2 grid of 32(M) x 64(N)
    int wid = tid >> 5;
    int lane = tid & 31;
    int mwarp = wid & 3;
    int nwarp = wid >> 2;
    int mt0 = mwarp * 2;
    int nt0 = nwarp * 8;

    float acc[2][8][4];
    #pragma unroll
    for (int i = 0; i < 2; i++)
        #pragma unroll
        for (int j = 0; j < 8; j++)
            #pragma unroll
            for (int q = 0; q < 4; q++) acc[i][j][q] = 0.f;

    #pragma unroll 1
    for (int seg = 0; seg < 3; seg++) {
        const uint4* aBuf = (const uint4*)(seg == 1 ? sAlo : sAhi);
        const uint2* bBuf = (const uint2*)(seg == 2 ? sBlo : sBhi);
        #pragma unroll 1
        for (int kt = 0; kt < 8; kt++) {
            uint4 afr[2];
            afr[0] = aBuf[(kt * 8 + mt0) * 32 + lane];
            afr[1] = aBuf[(kt * 8 + mt0 + 1) * 32 + lane];
            uint2 bfr[8];
            #pragma unroll
            for (int j = 0; j < 8; j++)
                bfr[j] = bBuf[(kt * 16 + nt0 + j) * 32 + lane];
            #pragma unroll
            for (int i = 0; i < 2; i++)
                #pragma unroll
                for (int j = 0; j < 8; j++)
                    mma16816(acc[i][j], afr[i], bfr[j]);
        }
    }

    // epilogue: bias + relu + store (dual)
    int rbase = m0 + mwarp * 32 + (lane >> 2);
    int cbase = nwarp * 64 + (lane & 3) * 2;
    #pragma unroll
    for (int i = 0; i < 2; i++) {
        #pragma unroll
        for (int j = 0; j < 8; j++) {
            int col = cbase + j * 8;
            float bx = BIAS ? bias[col] : 0.f;
            float by = BIAS ? bias[col + 1] : 0.f;
            int r0 = rbase + i * 16;
            if (r0 < Mrows) {
                float2 v;
                v.x = fmaxf(acc[i][j][0] + bx, 0.f);
                v.y = fmaxf(acc[i][j][1] + by, 0.f);
                *(float2*)&C[r0 * HD + col] = v;
                if (DUAL) *(float2*)&C2[r0 * HD + col] = v;
            }
            int r1 = rbase + i * 16 + 8;
            if (r1 < Mrows) {
                float2 v;
                v.x = fmaxf(acc[i][j][2] + bx, 0.f);
                v.y = fmaxf(acc[i][j][3] + by, 0.f);
                *(float2*)&C[r1 * HD + col] = v;
                if (DUAL) *(float2*)&C2[r1 * HD + col] = v;
            }
        }
    }
}

// -------- output GEMM: [M,128] @ [128,40] + bias (f32x2 inner) ------------
__global__ __launch_bounds__(320) void gemm_out(
    const float* __restrict__ A, const float* __restrict__ W,
    const float* __restrict__ bias, float* __restrict__ C, int Mrows)
{
    __shared__ float xs[128][33];
    __shared__ float ws[128][40];
    int tid = threadIdx.x;
    int m0 = blockIdx.x * 128;

    for (int idx = tid; idx < 128 * 40; idx += 320)
        ws[idx / 40][idx % 40] = W[idx];

    int slot = tid / 5;
    int cg = tid % 5;
    int r0 = slot, r1 = slot + 64;

    u64 acc[2][4];
    #pragma unroll
    for (int r = 0; r < 2; r++)
        #pragma unroll
        for (int j = 0; j < 4; j++) acc[r][j] = 0ull;

    for (int kc = 0; kc < HD; kc += 32) {
        __syncthreads();
        for (int idx = tid; idx < 128 * 32; idx += 320) {
            int r = idx >> 5, k = idx & 31;
            int m = min(m0 + r, Mrows - 1);
            xs[r][k] = A[m * HD + kc + k];
        }
        __syncthreads();
        #pragma unroll
        for (int k = 0; k < 32; k++) {
            u64 aa0 = bcast2(xs[r0][k]);
            u64 aa1 = bcast2(xs[r1][k]);
            ulonglong2 wp0 = *(const ulonglong2*)&ws[kc + k][cg * 8];
            ulonglong2 wp1 = *(const ulonglong2*)&ws[kc + k][cg * 8 + 4];
            ffma2(acc[0][0], aa0, wp0.x, acc[0][0]);
            ffma2(acc[0][1], aa0, wp0.y, acc[0][1]);
            ffma2(acc[0][2], aa0, wp1.x, acc[0][2]);
            ffma2(acc[0][3], aa0, wp1.y, acc[0][3]);
            ffma2(acc[1][0], aa1, wp0.x, acc[1][0]);
            ffma2(acc[1][1], aa1, wp0.y, acc[1][1]);
            ffma2(acc[1][2], aa1, wp1.x, acc[1][2]);
            ffma2(acc[1][3], aa1, wp1.y, acc[1][3]);
        }
    }

    #pragma unroll
    for (int r = 0; r < 2; r++) {
        int m = m0 + (r ? r1 : r0);
        if (m < Mrows) {
            float v[8];
            #pragma unroll
            for (int j2 = 0; j2 < 4; j2++) {
                float2 f = unpack2(acc[r][j2]);
                v[j2 * 2 + 0] = f.x + bias[cg * 8 + j2 * 2 + 0];
                v[j2 * 2 + 1] = f.y + bias[cg * 8 + j2 * 2 + 1];
            }
            float4* dst = (float4*)&C[m * NCLS + cg * 8];
            dst[0] = *(float4*)&v[0];
            dst[1] = *(float4*)&v[4];
        }
    }
}

// ---------------------------------------------------------------------
extern "C" void kernel_launch(void* const* d_in, const int* in_sizes, int n_in,
                              void* d_out, int out_size) {
    const float* x    = (const float*)d_in[0];
    const float* W0   = (const float*)d_in[1];
    const float* b0   = (const float*)d_in[2];
    const float* Ws   = (const float*)d_in[3];
    const float* Wout = (const float*)d_in[4];
    const float* bout = (const float*)d_in[5];
    const int* vtx    = (const int*)d_in[6];
    const int* edg    = (const int*)d_in[7];
    float* out = (float*)d_out;

    float *h, *h0, *Xi;
    cudaGetSymbolAddress((void**)&h,  g_h);
    cudaGetSymbolAddress((void**)&h0, g_h0);
    cudaGetSymbolAddress((void**)&Xi, g_Xi);

    cudaFuncSetAttribute(gemm_mma<true, true>,
                         cudaFuncAttributeMaxDynamicSharedMemorySize, GB_SMEM);
    cudaFuncSetAttribute(gemm_mma<false, false>,
                         cudaFuncAttributeMaxDynamicSharedMemorySize, GB_SMEM);

    const int gemmBlocks = (NV + 127) / 128;

    // CSR build
    k_zero_counts<<<(ME + NV + 255) / 256, 256>>>();
    k_count<<<(NNZE + 255) / 256, 256>>>(vtx, edg);
    k_scan<<<2, 1024>>>();
    k_fill<<<(NNZE + 255) / 256, 256>>>(vtx, edg);

    // weight prep: all 5 slots in one launch
    k_prep_frag<<<dim3((HD * HD + 255) / 256, 5), 256>>>(W0, Ws);

    // h = h0 = relu(x @ W0 + b0)
    gemm_mma<true, true><<<gemmBlocks, 256, GB_SMEM>>>(x, 0, b0, h, h0, NV);

    for (int i = 0; i < DEPTH; i++) {
        k_edge_agg<<<(ME * 32 + 255) / 256, 256>>>();
        k_vert_agg<<<(NV * 32 + 255) / 256, 256>>>();
        // h = relu(Xi @ ((1-b)I + b*Ws[i]))
        gemm_mma<false, false><<<gemmBlocks, 256, GB_SMEM>>>(Xi, i + 1, nullptr,
                                                            h, nullptr, NV);
    }

    gemm_out<<<gemmBlocks, 320>>>(h, Wout, bout, out, NV);
}